// round 1
// baseline (speedup 1.0000x reference)
#include <cuda_runtime.h>

// Encoding layer: B=16, D=128, N=H*W=4096, K=32
//   xc[b,n,k] = <X[b,n,:], C[k,:]>,  SL = scale[k]*(|X|^2 - 2 xc + |C[k]|^2)
//   A = softmax_k(SL),  E[b,k,d] = sum_n A[b,n,k]*X[b,n,d] - (sum_n A[b,n,k])*C[k,d]

#define Dd   128
#define Kk   32
#define Bb   16
#define HWn  4096
#define TN   64      // n per tile
#define CH   16      // chunks per batch
#define TILES 4      // tiles per chunk (TN*TILES*CH = 4096)
#define NTH  256

#define XS_STRIDE 68   // [d][n] rows, mult of 4 for 16B-aligned float4/double2
#define CS_STRIDE 132  // [k][d] rows
#define AS_STRIDE 33   // [n][k] rows

#define SMEM_FLOATS (128*XS_STRIDE + 32*CS_STRIDE + 64*AS_STRIDE + 64)
#define SMEM_BYTES  (SMEM_FLOATS*4)

// deterministic cross-chunk partials (no atomics anywhere)
__device__ float g_scratchE[Bb*CH*Kk*Dd];  // 4 MB
__device__ float g_scratchS[Bb*CH*Kk];

using u64 = unsigned long long;

__device__ __forceinline__ u64 pack2(float lo, float hi) {
    u64 r; asm("mov.b64 %0, {%1, %2};" : "=l"(r) : "f"(lo), "f"(hi)); return r;
}
__device__ __forceinline__ float2 unpack2(u64 v) {
    float2 f; asm("mov.b64 {%0, %1}, %2;" : "=f"(f.x), "=f"(f.y) : "l"(v)); return f;
}
// packed 2-wide fp32 FMA (PTX-only on sm_103a; 2x tput vs 3-reg FFMA)
__device__ __forceinline__ u64 fma2(u64 a, u64 b, u64 c) {
    u64 d; asm("fma.rn.f32x2 %0, %1, %2, %3;" : "=l"(d) : "l"(a), "l"(b), "l"(c)); return d;
}

__global__ void __launch_bounds__(NTH, 2) enc_main(
    const float* __restrict__ x,      // (B, D, H, W)
    const float* __restrict__ cw,     // (K, D)
    const float* __restrict__ scale)  // (K,)
{
    extern __shared__ float sm[];
    float* Xs  = sm;                       // [128][XS_STRIDE]   (d-major)
    float* Cs  = Xs + 128*XS_STRIDE;       // [32][CS_STRIDE]
    float* As  = Cs + 32*CS_STRIDE;        // [64][AS_STRIDE]
    float* c2s = As + 64*AS_STRIDE;        // [32]
    float* scs = c2s + 32;                 // [32]

    const int tid   = threadIdx.x;
    const int b     = blockIdx.y;
    const int chunk = blockIdx.x;

    // stage codewords
    #pragma unroll 1
    for (int i = tid; i < Kk*Dd; i += NTH)
        Cs[(i >> 7)*CS_STRIDE + (i & 127)] = cw[i];
    __syncthreads();
    if (tid < Kk) {
        float s = 0.f;
        #pragma unroll 1
        for (int d0 = 0; d0 < Dd; d0++) { float c = Cs[tid*CS_STRIDE + d0]; s += c*c; }
        c2s[tid] = s;
        scs[tid] = scale[tid];
    }
    // (visibility of c2s/scs guaranteed by loop-top __syncthreads below)

    u64 acc2[16];                  // phase-B accumulators: even/odd-n partial sums
    #pragma unroll
    for (int i = 0; i < 16; i++) acc2[i] = 0ull;
    float asum = 0.f;

    const int nloc = tid >> 2;        // phase A: n within tile (0..63)
    const int kg   = tid & 3;         // phase A: k = 4*j + kg
    const int kB   = tid & 31;        // phase B: k
    const int dsB  = (tid >> 5) * 16; // phase B: d slice base

    const float* xb = x + (size_t)b * Dd * HWn;

    for (int t = 0; t < TILES; t++) {
        const int n0 = chunk*(TN*TILES) + t*TN;
        __syncthreads();  // prior tile's phase B done before refill

        // ---- fill Xs[d][n] (coalesced float4 loads, conflict-free stores) ----
        #pragma unroll 1
        for (int i = tid; i < 128*16; i += NTH) {
            int d0 = i >> 4, n4 = (i & 15) << 2;
            float4 v = *(const float4*)(xb + (size_t)d0*HWn + n0 + n4);
            *(float4*)&Xs[d0*XS_STRIDE + n4] = v;
        }
        __syncthreads();

        // ---- phase A: xc[k] for k = 4j+kg, j=0..7 ----
        u64 xc2[8];
        #pragma unroll
        for (int j = 0; j < 8; j++) xc2[j] = 0ull;
        u64 x2p = 0ull;
        #pragma unroll 2
        for (int d0 = 0; d0 < 128; d0 += 4) {
            float xv0 = Xs[(d0+0)*XS_STRIDE + nloc];
            float xv1 = Xs[(d0+1)*XS_STRIDE + nloc];
            float xv2 = Xs[(d0+2)*XS_STRIDE + nloc];
            float xv3 = Xs[(d0+3)*XS_STRIDE + nloc];
            u64 xv01 = pack2(xv0, xv1), xv23 = pack2(xv2, xv3);
            x2p = fma2(xv01, xv01, x2p);
            x2p = fma2(xv23, xv23, x2p);
            #pragma unroll
            for (int j = 0; j < 8; j++) {
                double2 cdv = *(const double2*)&Cs[(4*j + kg)*CS_STRIDE + d0];
                xc2[j] = fma2(xv01, __double_as_longlong(cdv.x), xc2[j]);
                xc2[j] = fma2(xv23, __double_as_longlong(cdv.y), xc2[j]);
            }
        }
        float2 x2f = unpack2(x2p);
        float x2 = x2f.x + x2f.y;

        // ---- softmax over K=32 (4 lanes x 8 each, shfl-xor over kg lanes) ----
        float sl[8]; float m = -3.4e38f;
        #pragma unroll
        for (int j = 0; j < 8; j++) {
            int k = 4*j + kg;
            float2 xcf = unpack2(xc2[j]);
            float xc = xcf.x + xcf.y;
            sl[j] = scs[k] * (x2 - 2.f*xc + c2s[k]);
            m = fmaxf(m, sl[j]);
        }
        m = fmaxf(m, __shfl_xor_sync(0xffffffffu, m, 1));
        m = fmaxf(m, __shfl_xor_sync(0xffffffffu, m, 2));
        float ssum = 0.f;
        #pragma unroll
        for (int j = 0; j < 8; j++) { sl[j] = __expf(sl[j] - m); ssum += sl[j]; }
        ssum += __shfl_xor_sync(0xffffffffu, ssum, 1);
        ssum += __shfl_xor_sync(0xffffffffu, ssum, 2);
        float inv = 1.f / ssum;
        #pragma unroll
        for (int j = 0; j < 8; j++)
            As[nloc*AS_STRIDE + 4*j + kg] = sl[j] * inv;
        __syncthreads();

        // ---- phase B: E[k][dsB..dsB+15] += sum over 4-n groups ----
        #pragma unroll 1
        for (int nq = 0; nq < 16; nq++) {
            float a0 = As[(4*nq+0)*AS_STRIDE + kB];
            float a1 = As[(4*nq+1)*AS_STRIDE + kB];
            float a2 = As[(4*nq+2)*AS_STRIDE + kB];
            float a3 = As[(4*nq+3)*AS_STRIDE + kB];
            asum += (a0 + a1) + (a2 + a3);
            u64 a01 = pack2(a0, a1), a23 = pack2(a2, a3);
            #pragma unroll
            for (int i = 0; i < 16; i++) {
                // all lanes in a warp read the SAME address -> pure broadcast
                double2 xdv = *(const double2*)&Xs[(dsB + i)*XS_STRIDE + 4*nq];
                acc2[i] = fma2(a01, __double_as_longlong(xdv.x), acc2[i]);
                acc2[i] = fma2(a23, __double_as_longlong(xdv.y), acc2[i]);
            }
        }
    }

    // ---- epilogue: write per-chunk partials (deterministic, no atomics) ----
    float accf[16];
    #pragma unroll
    for (int i = 0; i < 16; i++) { float2 f = unpack2(acc2[i]); accf[i] = f.x + f.y; }
    float* eo = g_scratchE + (((size_t)(b*CH + chunk)*Kk + kB)*Dd + dsB);
    #pragma unroll
    for (int i = 0; i < 16; i += 4)
        *(float4*)(eo + i) = make_float4(accf[i], accf[i+1], accf[i+2], accf[i+3]);
    if ((tid >> 5) == 0)
        g_scratchS[(b*CH + chunk)*Kk + kB] = asum;
}

__global__ void enc_reduce(const float* __restrict__ cw, float* __restrict__ out)
{
    int idx = blockIdx.x*NTH + threadIdx.x;     // idx = ((b*K)+k)*D + d
    int b  = idx >> 12;
    int k  = (idx >> 7) & 31;
    int kd = idx & 4095;
    float e = 0.f, s = 0.f;
    #pragma unroll
    for (int ch = 0; ch < CH; ch++) {
        e += g_scratchE[(size_t)(b*CH + ch)*(Kk*Dd) + kd];
        s += g_scratchS[(b*CH + ch)*Kk + k];
    }
    out[idx] = e - s * cw[kd];
}

extern "C" void kernel_launch(void* const* d_in, const int* in_sizes, int n_in,
                              void* d_out, int out_size)
{
    const float* x  = (const float*)d_in[0];
    const float* cw = (const float*)d_in[1];
    const float* sc = (const float*)d_in[2];
    float* out = (float*)d_out;

    cudaFuncSetAttribute(enc_main, cudaFuncAttributeMaxDynamicSharedMemorySize, SMEM_BYTES);
    enc_main<<<dim3(CH, Bb), NTH, SMEM_BYTES>>>(x, cw, sc);
    enc_reduce<<<(Bb*Kk*Dd)/NTH, NTH>>>(cw, out);
}